// round 15
// baseline (speedup 1.0000x reference)
#include <cuda_runtime.h>
#include <cuda_bf16.h>
#include <cstdint>

#define IMG_H 480
#define IMG_W 640
#define IMG_HW (IMG_H * IMG_W)
#define OCH 64
#define KK 25
#define TKX 128          // CTA tile width (px)
#define TKY 4            // CTA tile rows -> 512 px per CTA
#define HW2 134          // halo tile cols
#define PW 140           // plane row stride (u32)
#define SP 36            // stage row stride (u32)
#define THREADS 256
#define THRESH 1e-4f

// ---- dynamic smem carve (bytes) ----
#define SCR_TILE 0                    // 8*134*4   = 4288   (t-gen scratch, dies)
#define SCR_RX   4352                 // 8*128*4   = 4096
#define SCR_RM   8448                 // 8*128*4   = 4096
#define OFF_STAGE 0                   // 8 warps * 64 * SP * 4 = 73728 (overlays scratch)
#define OFF_M2   73728                // 8*PW*4 = 4480
#define OFF_YH   78208
#define OFF_YL   82688
#define OFF_REF  87168                // 512*4 = 2048
#define SMEM_TOTAL 89216

// fragment-ordered split weights, K'=32 layout (kp j: dy=j/3, kw-pair 2*(j%3)):
// g_wfrag[((mt*32 + lane)*16) + term*8 + s*4 + r]
__device__ uint32_t g_wfrag[2048];

__device__ __forceinline__ uint32_t bf16x2_of(float lo, float hi) {
    uint32_t r;
    asm("cvt.rn.bf16x2.f32 %0, %1, %2;" : "=r"(r) : "f"(hi), "f"(lo));  // first src = high half
    return r;
}
__device__ __forceinline__ void mma16816(float* d, const uint32_t* a, const uint32_t* b) {
    asm volatile(
        "mma.sync.aligned.m16n8k16.row.col.f32.bf16.bf16.f32 "
        "{%0,%1,%2,%3}, {%4,%5,%6,%7}, {%8,%9}, {%0,%1,%2,%3};"
        : "+f"(d[0]), "+f"(d[1]), "+f"(d[2]), "+f"(d[3])
        : "r"(a[0]), "r"(a[1]), "r"(a[2]), "r"(a[3]), "r"(b[0]), "r"(b[1]));
}

__global__ void prep_wfrag(const float* __restrict__ wt) {
    int i = blockIdx.x * blockDim.x + threadIdx.x;   // 0..2047
    if (i >= 2048) return;
    int q    = i & 15;
    int lane = (i >> 4) & 31;
    int mt   = i >> 9;
    int term = q >> 3;
    int s    = (q >> 2) & 1;
    int r    = q & 3;
    int g = lane >> 2, tig = lane & 3;
    int ch = mt * 16 + g + ((r & 1) ? 8 : 0);
    int j  = 8 * s + tig + ((r >> 1) ? 4 : 0);       // kp row 0..15
    float w0 = 0.f, w1 = 0.f;
    if (j < 15) {
        int dy = j / 3, m = j - 3 * dy;
        int k0 = dy * 5 + 2 * m;
        w0 = wt[ch * KK + k0];
        if (2 * m + 1 < 5) w1 = wt[ch * KK + k0 + 1];
    }
    uint32_t h = bf16x2_of(w0, w1);
    uint32_t v = h;
    if (term) {
        float h0 = __uint_as_float(h << 16);
        float h1 = __uint_as_float(h & 0xffff0000u);
        v = bf16x2_of(w0 - h0, w1 - h1);
    }
    g_wfrag[i] = v;
}

__global__ __launch_bounds__(THREADS, 2)
void normdepthconv_plane_kernel(const float* __restrict__ x,
                                float* __restrict__ out) {
    extern __shared__ char sm[];
    float*    tile  = reinterpret_cast<float*>(sm + SCR_TILE);
    float*    rowsx = reinterpret_cast<float*>(sm + SCR_RX);
    float*    rowsm = reinterpret_cast<float*>(sm + SCR_RM);
    float*    stage = reinterpret_cast<float*>(sm + OFF_STAGE);   // overlays scratch
    uint32_t* m2    = reinterpret_cast<uint32_t*>(sm + OFF_M2);
    uint32_t* yh2   = reinterpret_cast<uint32_t*>(sm + OFF_YH);
    uint32_t* yl2   = reinterpret_cast<uint32_t*>(sm + OFF_YL);
    float*    refp  = reinterpret_cast<float*>(sm + OFF_REF);

    const int b   = blockIdx.z;
    const int X0  = blockIdx.x * TKX;
    const int Y0  = blockIdx.y * TKY;
    const int tid = threadIdx.x;
    const int lane = tid & 31;
    const int warp = tid >> 5;
    const int g    = lane >> 2;
    const int tig  = lane & 3;

    // warp partition: wrow = image row (0..3), half = nc range (0..1)
    const int wrow = warp >> 1;
    const int half = warp & 1;

    // ---- weight fragments for ALL 4 mt: 16x LDG.128, early for MLP ----
    uint32_t Wh[4][2][4], Wl[4][2][4];
#pragma unroll
    for (int m = 0; m < 4; ++m) {
        const uint4* wp =
            reinterpret_cast<const uint4*>(g_wfrag + (m * 32 + lane) * 16);
        uint4 u0 = wp[0], u1 = wp[1], u2 = wp[2], u3 = wp[3];
        Wh[m][0][0] = u0.x; Wh[m][0][1] = u0.y; Wh[m][0][2] = u0.z; Wh[m][0][3] = u0.w;
        Wh[m][1][0] = u1.x; Wh[m][1][1] = u1.y; Wh[m][1][2] = u1.z; Wh[m][1][3] = u1.w;
        Wl[m][0][0] = u2.x; Wl[m][0][1] = u2.y; Wl[m][0][2] = u2.z; Wl[m][0][3] = u2.w;
        Wl[m][1][0] = u3.x; Wl[m][1][1] = u3.y; Wl[m][1][2] = u3.z; Wl[m][1][3] = u3.w;
    }

    // ---- halo tile load (zero-padded borders), 8 rows ----
    const float* xb = x + (size_t)b * IMG_HW;
    for (int i = tid; i < 8 * HW2; i += THREADS) {
        int r = i / HW2, c = i - r * HW2;
        int gy = Y0 - 2 + r, gx = X0 - 2 + c;
        float v = 0.f;
        if (gy >= 0 && gy < IMG_H && gx >= 0 && gx < IMG_W) v = xb[gy * IMG_W + gx];
        tile[i] = v;
    }
    __syncthreads();

    // ---- 5-tap row sums (x, mask) + bf16 plane generation ----
    for (int q = tid; q < 8 * 128; q += THREADS) {
        int r = q >> 7, i = q & 127;
        const float* tr = &tile[r * HW2 + i];
        float sx = 0.f, smv = 0.f;
#pragma unroll
        for (int kw = 0; kw < 5; ++kw) {
            float v = tr[kw];
            sx += v;
            smv += (v > THRESH) ? 1.f : 0.f;
        }
        rowsx[q] = sx;
        rowsm[q] = smv;
    }
    for (int q = tid; q < 8 * 132; q += THREADS) {
        int r = q / 132, h = q - r * 132;
        float x0 = tile[r * HW2 + h], x1 = tile[r * HW2 + h + 1];
        float mk0 = (x0 > THRESH) ? 1.f : 0.f;
        float mk1 = (x1 > THRESH) ? 1.f : 0.f;
        float y0 = x0 * mk0, y1 = x1 * mk1;
        uint32_t hh = bf16x2_of(y0, y1);
        float e0 = y0 - __uint_as_float(hh << 16);
        float e1 = y1 - __uint_as_float(hh & 0xffff0000u);
        m2 [r * PW + h] = bf16x2_of(mk0, mk1);
        yh2[r * PW + h] = hh;
        yl2[r * PW + h] = bf16x2_of(e0, e1);
    }
    __syncthreads();

    // ---- 5-tap column sums -> ref per output pixel (512 px) ----
    for (int q = tid; q < 512; q += THREADS) {
        int ry = q >> 7, i = q & 127;
        float Sx = 0.f, Sm = 0.f;
#pragma unroll
        for (int dy = 0; dy < 5; ++dy) {
            Sx += rowsx[(ry + dy) * 128 + i];
            Sm += rowsm[(ry + dy) * 128 + i];
        }
        refp[q] = Sx / (Sm + 1e-6f);
    }
    __syncthreads();   // scratch (tile/rowsx/rowsm) dead -> stage may overwrite

    // ---- fragment gather offsets (loop-invariant): j = 8s + tig (+4) ----
    int ofs[2][2];
#pragma unroll
    for (int s = 0; s < 2; ++s) {
#pragma unroll
        for (int ri = 0; ri < 2; ++ri) {
            int j = 8 * s + tig + 4 * ri;
            int dy = 0, m = 0;
            if (j < 15) { dy = j / 3; m = j - 3 * dy; }
            ofs[s][ri] = dy * PW + 2 * m;
        }
    }

    // ---- GEMM: warp = 64 px (row wrow, half) x ALL 64 ch ----
    float* wb = stage + warp * (64 * SP);
    float* obase = out + (size_t)b * OCH * IMG_HW + (size_t)(Y0 + wrow) * IMG_W + X0;
    const int pbase = wrow * PW;
    const int rr  = lane >> 3;             // drain row-in-quad
    const int pxl = 4 * (lane & 7);        // drain px offset

#pragma unroll 1
    for (int gi = 0; gi < 2; ++gi) {       // 2 groups of 32 px
#pragma unroll
        for (int ncl = 0; ncl < 4; ++ncl) {
            const int nc = half * 8 + gi * 4 + ncl;
            const int base = pbase + nc * 8 + g;

            uint32_t bm[2][2], by[2][2], bl[2][2];
#pragma unroll
            for (int s = 0; s < 2; ++s) {
#pragma unroll
                for (int ri = 0; ri < 2; ++ri) {
                    int a = base + ofs[s][ri];
                    bm[s][ri] = m2 [a];
                    by[s][ri] = yh2[a];
                    bl[s][ri] = yl2[a];
                }
            }

            float accA[4][4], accB[4][4];
#pragma unroll
            for (int m = 0; m < 4; ++m)
#pragma unroll
                for (int r = 0; r < 4; ++r) { accA[m][r] = 0.f; accB[m][r] = 0.f; }

#pragma unroll
            for (int s = 0; s < 2; ++s) {
#pragma unroll
                for (int m = 0; m < 4; ++m) {
                    mma16816(accA[m], Wh[m][s], bm[s]);
                    mma16816(accB[m], Wh[m][s], by[s]);
                    mma16816(accA[m], Wl[m][s], bm[s]);
                    mma16816(accB[m], Wl[m][s], by[s]);
                    mma16816(accB[m], Wh[m][s], bl[s]);
                }
            }

            // ref*A - B -> stage (row = ch, col = ncl*8 + 2*tig)
            const float2 rv =
                *reinterpret_cast<const float2*>(&refp[wrow * 128 + nc * 8 + 2 * tig]);
            const int colo = ncl * 8 + 2 * tig;
#pragma unroll
            for (int m = 0; m < 4; ++m) {
                *reinterpret_cast<float2*>(&wb[(m * 16 + g) * SP + colo]) =
                    make_float2(fmaf(rv.x, accA[m][0], -accB[m][0]),
                                fmaf(rv.y, accA[m][1], -accB[m][1]));
                *reinterpret_cast<float2*>(&wb[(m * 16 + 8 + g) * SP + colo]) =
                    make_float2(fmaf(rv.x, accA[m][2], -accB[m][2]),
                                fmaf(rv.y, accA[m][3], -accB[m][3]));
            }
        }
        __syncwarp();

        // coalesced drain: 16x (LDS.128 + STG.128 over 4 full 128B lines)
        const int gcol = half * 64 + gi * 32;
#pragma unroll
        for (int it = 0; it < 16; ++it) {
            const int r = it * 4 + rr;     // ch 0..63
            float4 v = *reinterpret_cast<const float4*>(&wb[r * SP + pxl]);
            *reinterpret_cast<float4*>(obase + (size_t)r * IMG_HW + gcol + pxl) = v;
        }
        __syncwarp();
    }
}

extern "C" void kernel_launch(void* const* d_in, const int* in_sizes, int n_in,
                              void* d_out, int out_size) {
    const float* x = (const float*)d_in[0];
    const float* w = (const float*)d_in[1];
    if (n_in >= 2 && in_sizes[0] == OCH * KK) {   // defensive input-order check
        x = (const float*)d_in[1];
        w = (const float*)d_in[0];
    }
    prep_wfrag<<<16, 128>>>(w);
    cudaFuncSetAttribute(normdepthconv_plane_kernel,
                         cudaFuncAttributeMaxDynamicSharedMemorySize, SMEM_TOTAL);
    dim3 grid(IMG_W / TKX, IMG_H / TKY, 8);   // 5 x 120 x 8 = 4800 CTAs
    normdepthconv_plane_kernel<<<grid, THREADS, SMEM_TOTAL>>>(x, (float*)d_out);
}

// round 17
// speedup vs baseline: 1.3244x; 1.3244x over previous
#include <cuda_runtime.h>
#include <cuda_bf16.h>
#include <cstdint>

#define IMG_H 480
#define IMG_W 640
#define IMG_HW (IMG_H * IMG_W)
#define OCH 64
#define KK 25
#define TKX 128          // CTA tile width (px)
#define TKY 2            // CTA tile rows -> 256 px per CTA
#define HW2 134          // halo tile cols
#define PW 140           // plane row stride (u32)
#define SP 36            // stage row stride (u32)
#define THREADS 128
#define THRESH 1e-4f

// fragment-ordered split weights, K'=32 layout (kp j: dy=j/3, kw-pair 2*(j%3)):
// g_wfrag[((mt*32 + lane)*16) + term*8 + s*4 + r]
__device__ uint32_t g_wfrag[2048];
__device__ float    g_sumw[OCH];        // exact fp32 per-channel weight sums

__device__ __forceinline__ uint32_t bf16x2_of(float lo, float hi) {
    uint32_t r;
    asm("cvt.rn.bf16x2.f32 %0, %1, %2;" : "=r"(r) : "f"(hi), "f"(lo));  // first src = high half
    return r;
}
__device__ __forceinline__ void mma16816(float* d, const uint32_t* a, const uint32_t* b) {
    asm volatile(
        "mma.sync.aligned.m16n8k16.row.col.f32.bf16.bf16.f32 "
        "{%0,%1,%2,%3}, {%4,%5,%6,%7}, {%8,%9}, {%0,%1,%2,%3};"
        : "+f"(d[0]), "+f"(d[1]), "+f"(d[2]), "+f"(d[3])
        : "r"(a[0]), "r"(a[1]), "r"(a[2]), "r"(a[3]), "r"(b[0]), "r"(b[1]));
}

__global__ void prep_wfrag(const float* __restrict__ wt) {
    int i = blockIdx.x * blockDim.x + threadIdx.x;   // 0..2047
    if (i >= 2048) return;
    if (i < OCH) {                       // exact channel sums
        float s = 0.f;
        for (int k = 0; k < KK; ++k) s += wt[i * KK + k];
        g_sumw[i] = s;
    }
    int q    = i & 15;
    int lane = (i >> 4) & 31;
    int mt   = i >> 9;
    int term = q >> 3;
    int s    = (q >> 2) & 1;
    int r    = q & 3;
    int g = lane >> 2, tig = lane & 3;
    int ch = mt * 16 + g + ((r & 1) ? 8 : 0);
    int j  = 8 * s + tig + ((r >> 1) ? 4 : 0);       // kp row 0..15
    float w0 = 0.f, w1 = 0.f;
    if (j < 15) {
        int dy = j / 3, m = j - 3 * dy;
        int k0 = dy * 5 + 2 * m;
        w0 = wt[ch * KK + k0];
        if (2 * m + 1 < 5) w1 = wt[ch * KK + k0 + 1];
    }
    uint32_t h = bf16x2_of(w0, w1);
    uint32_t v = h;
    if (term) {
        float h0 = __uint_as_float(h << 16);
        float h1 = __uint_as_float(h & 0xffff0000u);
        v = bf16x2_of(w0 - h0, w1 - h1);
    }
    g_wfrag[i] = v;
}

__global__ __launch_bounds__(THREADS, 5)
void normdepthconv_plane_kernel(const float* __restrict__ x,
                                float* __restrict__ out) {
    __shared__ float    tile[6 * HW2];
    __shared__ float    rowsx[6 * 128];
    __shared__ float    rowsm[6 * 128];
    __shared__ float    refp[256];
    __shared__ uint32_t m2 [6 * PW];
    __shared__ uint32_t yh2[6 * PW];
    __shared__ uint32_t yl2[6 * PW];
    __shared__ __align__(16) float stage[4 * 32 * SP];

    const int b   = blockIdx.z;
    const int X0  = blockIdx.x * TKX;
    const int Y0  = blockIdx.y * TKY;
    const int tid = threadIdx.x;
    const int lane = tid & 31;
    const int warp = tid >> 5;
    const int g    = lane >> 2;
    const int tig  = lane & 3;

    const int wrow = warp >> 1;            // 0 or 1
    const int mt0  = (warp & 1) * 2;       // {0,1} or {2,3}

    // ---- weight fragments for mt0, mt0+1 ----
    uint32_t Wh[2][2][4], Wl[2][2][4];
#pragma unroll
    for (int m = 0; m < 2; ++m) {
        const uint4* wp =
            reinterpret_cast<const uint4*>(g_wfrag + ((mt0 + m) * 32 + lane) * 16);
        uint4 u0 = wp[0], u1 = wp[1], u2 = wp[2], u3 = wp[3];
        Wh[m][0][0] = u0.x; Wh[m][0][1] = u0.y; Wh[m][0][2] = u0.z; Wh[m][0][3] = u0.w;
        Wh[m][1][0] = u1.x; Wh[m][1][1] = u1.y; Wh[m][1][2] = u1.z; Wh[m][1][3] = u1.w;
        Wl[m][0][0] = u2.x; Wl[m][0][1] = u2.y; Wl[m][0][2] = u2.z; Wl[m][0][3] = u2.w;
        Wl[m][1][0] = u3.x; Wl[m][1][1] = u3.y; Wl[m][1][2] = u3.z; Wl[m][1][3] = u3.w;
    }
    // exact A-values for fast path: sumw for this lane's 4 channels
    float swA[2], swB[2];
#pragma unroll
    for (int m = 0; m < 2; ++m) {
        swA[m] = g_sumw[(mt0 + m) * 16 + g];
        swB[m] = g_sumw[(mt0 + m) * 16 + 8 + g];
    }

    // ---- halo tile load + all-valid vote ----
    const float* xb = x + (size_t)b * IMG_HW;
    int ok = 1;
    for (int i = tid; i < 6 * HW2; i += THREADS) {
        int r = i / HW2, c = i - r * HW2;
        int gy = Y0 - 2 + r, gx = X0 - 2 + c;
        float v = 0.f;
        if (gy >= 0 && gy < IMG_H && gx >= 0 && gx < IMG_W) v = xb[gy * IMG_W + gx];
        tile[i] = v;
        ok &= (v > THRESH) ? 1 : 0;
    }
    const bool fast = __syncthreads_and(ok) != 0;

    // ---- 5-tap row sums + bf16 plane generation ----
    for (int q = tid; q < 6 * 128; q += THREADS) {
        int r = q >> 7, i = q & 127;
        const float* tr = &tile[r * HW2 + i];
        float sx = 0.f, smv = 0.f;
#pragma unroll
        for (int kw = 0; kw < 5; ++kw) {
            float v = tr[kw];
            sx += v;
            smv += (v > THRESH) ? 1.f : 0.f;
        }
        rowsx[q] = sx;
        if (!fast) rowsm[q] = smv;
    }
    for (int q = tid; q < 6 * 132; q += THREADS) {
        int r = q / 132, h = q - r * 132;
        float x0 = tile[r * HW2 + h], x1 = tile[r * HW2 + h + 1];
        float mk0 = (x0 > THRESH) ? 1.f : 0.f;
        float mk1 = (x1 > THRESH) ? 1.f : 0.f;
        float y0 = x0 * mk0, y1 = x1 * mk1;
        uint32_t hh = bf16x2_of(y0, y1);
        float e0 = y0 - __uint_as_float(hh << 16);
        float e1 = y1 - __uint_as_float(hh & 0xffff0000u);
        yh2[r * PW + h] = hh;
        yl2[r * PW + h] = bf16x2_of(e0, e1);
        if (!fast) m2[r * PW + h] = bf16x2_of(mk0, mk1);
    }
    __syncthreads();

    // ---- column sums -> ref ----
    for (int q = tid; q < 256; q += THREADS) {
        int ry = q >> 7, i = q & 127;
        float Sx = 0.f;
#pragma unroll
        for (int dy = 0; dy < 5; ++dy) Sx += rowsx[(ry + dy) * 128 + i];
        if (fast) {
            refp[q] = Sx / (25.f + 1e-6f);
        } else {
            float Sm = 0.f;
#pragma unroll
            for (int dy = 0; dy < 5; ++dy) Sm += rowsm[(ry + dy) * 128 + i];
            refp[q] = Sx / (Sm + 1e-6f);
        }
    }
    __syncthreads();

    // ---- fragment gather offsets ----
    int ofs[2][2];
#pragma unroll
    for (int s = 0; s < 2; ++s) {
#pragma unroll
        for (int ri = 0; ri < 2; ++ri) {
            int j = 8 * s + tig + 4 * ri;
            int dy = 0, m = 0;
            if (j < 15) { dy = j / 3; m = j - 3 * dy; }
            ofs[s][ri] = dy * PW + 2 * m;
        }
    }

    float* wb = stage + warp * (32 * SP);
    float* obase = out + (size_t)b * OCH * IMG_HW + (size_t)(mt0 * 16) * IMG_HW +
                   (size_t)(Y0 + wrow) * IMG_W + X0;
    const int pbase = wrow * PW;
    const int rr  = lane >> 3;
    const int pxl = 4 * (lane & 7);

    if (fast) {
        // ================= FAST PATH: A = sumw exactly, B-side GEMM only =========
#pragma unroll 1
        for (int gi = 0; gi < 4; ++gi) {
#pragma unroll
            for (int ncl = 0; ncl < 4; ++ncl) {
                const int nc = gi * 4 + ncl;
                const int base = pbase + nc * 8 + g;
                uint32_t by[2][2], bl[2][2];
#pragma unroll
                for (int s = 0; s < 2; ++s) {
#pragma unroll
                    for (int ri = 0; ri < 2; ++ri) {
                        int a = base + ofs[s][ri];
                        by[s][ri] = yh2[a];
                        bl[s][ri] = yl2[a];
                    }
                }
                float accB[2][4] = {{0.f, 0.f, 0.f, 0.f}, {0.f, 0.f, 0.f, 0.f}};
#pragma unroll
                for (int s = 0; s < 2; ++s) {
#pragma unroll
                    for (int m = 0; m < 2; ++m) {
                        mma16816(accB[m], Wh[m][s], by[s]);
                        mma16816(accB[m], Wl[m][s], by[s]);
                        mma16816(accB[m], Wh[m][s], bl[s]);
                    }
                }
                const int xo = nc * 8 + 2 * tig;
                const float2 rv = *reinterpret_cast<const float2*>(&refp[wrow * 128 + xo]);
                const int colo = ncl * 8 + 2 * tig;
#pragma unroll
                for (int m = 0; m < 2; ++m) {
                    *reinterpret_cast<float2*>(&wb[(m * 16 + g) * SP + colo]) =
                        make_float2(fmaf(rv.x, swA[m], -accB[m][0]),
                                    fmaf(rv.y, swA[m], -accB[m][1]));
                    *reinterpret_cast<float2*>(&wb[(m * 16 + 8 + g) * SP + colo]) =
                        make_float2(fmaf(rv.x, swB[m], -accB[m][2]),
                                    fmaf(rv.y, swB[m], -accB[m][3]));
                }
            }
            __syncwarp();
#pragma unroll
            for (int it = 0; it < 8; ++it) {
                const int r = it * 4 + rr;
                float4 v = *reinterpret_cast<const float4*>(&wb[r * SP + pxl]);
                *reinterpret_cast<float4*>(obase + (size_t)r * IMG_HW + gi * 32 + pxl) = v;
            }
            __syncwarp();
        }
    } else {
        // ================= SLOW PATH: full R14 GEMM (verbatim) ====================
#pragma unroll 1
        for (int gi = 0; gi < 4; ++gi) {
#pragma unroll
            for (int ncl = 0; ncl < 4; ++ncl) {
                const int nc = gi * 4 + ncl;
                const int base = pbase + nc * 8 + g;
                uint32_t bm[2][2], by[2][2], bl[2][2];
#pragma unroll
                for (int s = 0; s < 2; ++s) {
#pragma unroll
                    for (int ri = 0; ri < 2; ++ri) {
                        int a = base + ofs[s][ri];
                        bm[s][ri] = m2 [a];
                        by[s][ri] = yh2[a];
                        bl[s][ri] = yl2[a];
                    }
                }
                float accA[2][4] = {{0.f, 0.f, 0.f, 0.f}, {0.f, 0.f, 0.f, 0.f}};
                float accB[2][4] = {{0.f, 0.f, 0.f, 0.f}, {0.f, 0.f, 0.f, 0.f}};
#pragma unroll
                for (int s = 0; s < 2; ++s) {
#pragma unroll
                    for (int m = 0; m < 2; ++m) {
                        mma16816(accA[m], Wh[m][s], bm[s]);
                        mma16816(accB[m], Wh[m][s], by[s]);
                        mma16816(accA[m], Wl[m][s], bm[s]);
                        mma16816(accB[m], Wl[m][s], by[s]);
                        mma16816(accB[m], Wh[m][s], bl[s]);
                    }
                }
                const int xo = nc * 8 + 2 * tig;
                const float2 rv = *reinterpret_cast<const float2*>(&refp[wrow * 128 + xo]);
                const int colo = ncl * 8 + 2 * tig;
#pragma unroll
                for (int m = 0; m < 2; ++m) {
                    *reinterpret_cast<float2*>(&wb[(m * 16 + g) * SP + colo]) =
                        make_float2(fmaf(rv.x, accA[m][0], -accB[m][0]),
                                    fmaf(rv.y, accA[m][1], -accB[m][1]));
                    *reinterpret_cast<float2*>(&wb[(m * 16 + 8 + g) * SP + colo]) =
                        make_float2(fmaf(rv.x, accA[m][2], -accB[m][2]),
                                    fmaf(rv.y, accA[m][3], -accB[m][3]));
                }
            }
            __syncwarp();
#pragma unroll
            for (int it = 0; it < 8; ++it) {
                const int r = it * 4 + rr;
                float4 v = *reinterpret_cast<const float4*>(&wb[r * SP + pxl]);
                *reinterpret_cast<float4*>(obase + (size_t)r * IMG_HW + gi * 32 + pxl) = v;
            }
            __syncwarp();
        }
    }
}

extern "C" void kernel_launch(void* const* d_in, const int* in_sizes, int n_in,
                              void* d_out, int out_size) {
    const float* x = (const float*)d_in[0];
    const float* w = (const float*)d_in[1];
    if (n_in >= 2 && in_sizes[0] == OCH * KK) {   // defensive input-order check
        x = (const float*)d_in[1];
        w = (const float*)d_in[0];
    }
    prep_wfrag<<<16, 128>>>(w);
    dim3 grid(IMG_W / TKX, IMG_H / TKY, 8);   // 5 x 240 x 8 = 9600 CTAs
    normdepthconv_plane_kernel<<<grid, THREADS>>>(x, (float*)d_out);
}